// round 14
// baseline (speedup 1.0000x reference)
#include <cuda_runtime.h>

// ---------------------------------------------------------------------------
// DifferentiableRenderer: Gaussian splat weighted-average render.
// out[b,c,y,x] = sum_n w_n*color_n / (sum_n w_n + 1e-8)
// w_n = opacity_n * exp(-0.5*((x-u_n)^2+(y-v_n)^2)/var_n)
//
// R14: fix load imbalance. Survivors are heavily skewed (center tiles see
//   ~2000 gaussians, corners ~0); at SPLIT=4 one block carried ~7us of fma
//   work and gated the kernel. SPLIT=16 divides the hot spots 4x at ZERO
//   extra prep cost (total prep-culls = B*TILES*N, SPLIT-invariant).
//   Single kernel, last-arriving block per tile merges via one
//   atom.acq_rel.gpu (no MEMBAR drain), fixed slice order (deterministic),
//   resets counter for graph replay. Cut at w < 2^-60: abs err ~7e-7.
// ---------------------------------------------------------------------------

#define HH 128
#define WW 128
#define HWP (HH * WW)
#define FXC 150.0f
#define FYC 150.0f
#define CXC 64.0f
#define CYC 64.0f
#define EPSC 1e-8f

#define TILE    16
#define TX_N    (WW / TILE)          // 8
#define TY_N    (HH / TILE)          // 8
#define TILES   (TX_N * TY_N)        // 64
#define SPLIT   16                   // gaussian slices per tile (power of 2)
#define TPB     256                  // threads per render block (1 px each)
#define CHUNK   256                  // gaussians prepped+tested per pass
#define EMIN    (-60.0f)             // log2 weight cutoff

#define MAXB    4

// per (b, tile, split, pixel) partial sums {den, r, g, b} -- L2 resident
__device__ float4 g_part[MAXB * TILES * SPLIT * TPB];
// per (b, tile) arrival counters (zero-init; reset by merging block)
__device__ int g_cnt[MAXB * TILES];

__device__ __forceinline__ float ex2f(float x) {
    float y;
    asm("ex2.approx.ftz.f32 %0, %1;" : "=f"(y) : "f"(x));
    return y;
}
__device__ __forceinline__ float lg2f(float x) {
    float y;
    asm("lg2.approx.ftz.f32 %0, %1;" : "=f"(y) : "f"(x));
    return y;
}
// fetch-add with acq_rel at gpu scope: releases our prior stores, acquires
// peers' released stores. No MEMBAR drain.
__device__ __forceinline__ int atom_add_acqrel(int* p, int v) {
    int old;
    asm volatile("atom.add.acq_rel.gpu.global.s32 %0, [%1], %2;"
                 : "=r"(old) : "l"(p), "r"(v) : "memory");
    return old;
}

// ---------------------------------------------------------------------------
// blockIdx.x = ((b*TILES + tile)*SPLIT + s). 256 threads = one 16x16 tile.
// ---------------------------------------------------------------------------
__global__ void __launch_bounds__(TPB)
render_tiles(float* __restrict__ out,
             const float* __restrict__ pos,
             const float* __restrict__ col,
             const float* __restrict__ opac,
             const float* __restrict__ scal,
             const float* __restrict__ qv,
             const float* __restrict__ tv,
             int N) {
    __shared__ float4 sga[CHUNK];      // u, v, a, bop
    __shared__ float4 sgb[CHUNK];      // cr, cg, cb, -
    __shared__ int s_wbase[TPB / 32];
    __shared__ int s_wcnt[TPB / 32];
    __shared__ int s_total;
    __shared__ int s_arrival;

    const int tid  = threadIdx.x;
    const int bid  = blockIdx.x;
    const int s    = bid & (SPLIT - 1);
    const int tile = (bid / SPLIT) & (TILES - 1);
    const int b    = bid / (SPLIT * TILES);
    const int m    = b * TILES + tile;            // tile slot

    const int tx = tile & (TX_N - 1);
    const int ty = tile / TX_N;
    const float pxf = (float)(tx * TILE + (tid & (TILE - 1)));
    const float pyf = (float)(ty * TILE + (tid / TILE));
    const float tcx = (float)(tx * TILE) + 7.5f;   // tile center
    const float tcy = (float)(ty * TILE) + 7.5f;

    // --- per-batch camera, hoisted (broadcast loads, L1 hits) ---
    float qw = qv[b * 4 + 0], qx = qv[b * 4 + 1];
    float qy = qv[b * 4 + 2], qz = qv[b * 4 + 3];
    {
        float inv = rsqrtf(qw * qw + qx * qx + qy * qy + qz * qz);
        qw *= inv; qx *= inv; qy *= inv; qz *= inv;
    }
    const float R00 = 1.0f - 2.0f * (qy * qy + qz * qz);
    const float R01 = 2.0f * (qx * qy - qz * qw);
    const float R02 = 2.0f * (qx * qz + qy * qw);
    const float R10 = 2.0f * (qx * qy + qz * qw);
    const float R11 = 1.0f - 2.0f * (qx * qx + qz * qz);
    const float R12 = 2.0f * (qy * qz - qx * qw);
    const float R20 = 2.0f * (qx * qz - qy * qw);
    const float R21 = 2.0f * (qy * qz + qx * qw);
    const float R22 = 1.0f - 2.0f * (qx * qx + qy * qy);
    const float t0 = tv[b * 3 + 0], t1 = tv[b * 3 + 1], t2 = tv[b * 3 + 2];

    const int lo = (s * N) / SPLIT;
    const int hi = ((s + 1) * N) / SPLIT;

    const int wid  = tid >> 5;
    const int lane = tid & 31;
    const unsigned lanemask_lt = (1u << lane) - 1u;

    float den = 0.f, ar = 0.f, ag = 0.f, ab = 0.f;

    for (int cb = lo; cb < hi; cb += CHUNK) {
        // --- prep + cull one gaussian per thread ---
        const int j = cb + tid;                    // gaussian index
        bool keep = false;
        float4 ga;
        if (j < hi) {
            const float px = pos[j * 3 + 0];
            const float py = pos[j * 3 + 1];
            const float pz = pos[j * 3 + 2];
            const float cxm = R00 * px + R01 * py + R02 * pz + t0;
            const float cym = R10 * px + R11 * py + R12 * pz + t1;
            const float czm = R20 * px + R21 * py + R22 * pz + t2;
            const float invz = __fdividef(1.0f, czm);
            const float u = cxm * invz * FXC + CXC;
            const float v = cym * invz * FYC + CYC;
            const float sc = scal[j];
            // a = -0.5 * log2(e) / var
            const float a = __fdividef(-0.72134752044448170f, sc * sc);
            const float bop = lg2f(opac[j]);       // opac=0 -> -inf -> culled
            ga = make_float4(u, v, a, bop);

            float dx = fmaxf(fabsf(u - tcx) - 7.5f, 0.0f);
            float dy = fmaxf(fabsf(v - tcy) - 7.5f, 0.0f);
            float mind2 = dx * dx + dy * dy;
            float emax  = fmaf(a, mind2, bop);     // a*mind2 + bop (a<0)
            keep = (emax >= EMIN);
        }

        // --- stable compaction (gaussian-index order preserved) ---
        const unsigned mask = __ballot_sync(0xffffffffu, keep);
        if (lane == 0) s_wcnt[wid] = __popc(mask);
        __syncthreads();
        if (tid == 0) {
            int acc = 0;
            #pragma unroll
            for (int w = 0; w < TPB / 32; w++) { s_wbase[w] = acc; acc += s_wcnt[w]; }
            s_total = acc;
        }
        __syncthreads();
        if (keep) {
            const int posn = s_wbase[wid] + __popc(mask & lanemask_lt);
            sga[posn] = ga;
            sgb[posn] = make_float4(col[j * 3 + 0], col[j * 3 + 1],
                                    col[j * 3 + 2], 0.0f);
        }
        __syncthreads();

        // --- evaluate survivors against this thread's pixel ---
        const int cnt = s_total;
        #pragma unroll 2
        for (int t = 0; t < cnt; t++) {
            const float4 A  = sga[t];              // u, v, a, bop (broadcast)
            const float4 Cc = sgb[t];
            const float dv = pyf - A.y;
            const float c2 = fmaf(A.z * dv, dv, A.w);
            const float du = pxf - A.x;
            const float e  = fmaf(A.z * du, du, c2);
            const float w  = ex2f(e);
            den += w;
            ar = fmaf(w, Cc.x, ar);
            ag = fmaf(w, Cc.y, ag);
            ab = fmaf(w, Cc.z, ab);
        }
        __syncthreads();
    }

    // --- publish this slice's partial to L2 ---
    __stcg(&g_part[bid * TPB + tid], make_float4(den, ar, ag, ab));
    __syncthreads();   // intra-block HB: all stores precede tid0's release

    // --- last-arriving block of this tile merges ---
    if (tid == 0) s_arrival = atom_add_acqrel(&g_cnt[m], 1);
    __syncthreads();   // acquire by tid0 + barrier -> HB for all readers

    if (s_arrival == SPLIT - 1) {
        // all SPLIT partials for tile m visible in L2 (release/acquire chain)
        // fixed slice order -> deterministic regardless of merger identity
        float4 acc = make_float4(0.f, 0.f, 0.f, 0.f);
        #pragma unroll
        for (int sl = 0; sl < SPLIT; sl++) {
            const float4 p = __ldcg(&g_part[(m * SPLIT + sl) * TPB + tid]);
            acc.x += p.x; acc.y += p.y; acc.z += p.z; acc.w += p.w;
        }

        const float invd = __fdividef(1.0f, acc.x + EPSC);

        const int px = tx * TILE + (tid & (TILE - 1));
        const int py = ty * TILE + (tid / TILE);
        float* ob = out + (size_t)b * 3 * HWP + py * WW + px;
        ob[0]       = acc.y * invd;   // R plane
        ob[HWP]     = acc.z * invd;   // G plane
        ob[2 * HWP] = acc.w * invd;   // B plane

        if (tid == 0) g_cnt[m] = 0;   // reset for next launch / graph replay
    }
}

// ---------------------------------------------------------------------------
extern "C" void kernel_launch(void* const* d_in, const int* in_sizes, int n_in,
                              void* d_out, int out_size) {
    const float* positions = (const float*)d_in[0];
    const float* colors    = (const float*)d_in[1];
    const float* opacities = (const float*)d_in[2];
    const float* scales    = (const float*)d_in[3];
    const float* qvec      = (const float*)d_in[4];
    const float* tvec      = (const float*)d_in[5];
    float* out = (float*)d_out;

    const int N = in_sizes[0] / 3;
    const int B = in_sizes[4] / 4;

    render_tiles<<<B * TILES * SPLIT, TPB>>>(out, positions, colors, opacities,
                                             scales, qvec, tvec, N);
}

// round 15
// speedup vs baseline: 1.2635x; 1.2635x over previous
#include <cuda_runtime.h>

// ---------------------------------------------------------------------------
// DifferentiableRenderer: Gaussian splat weighted-average render.
// out[b,c,y,x] = sum_n w_n*color_n / (sum_n w_n + 1e-8)
// w_n = opacity_n * exp(-0.5*((x-u_n)^2+(y-v_n)^2)/var_n)
//
// R15: eval loop is issue-bound (~12 slots/interaction-pair at 32% issue
//   reproduces the measured 10.2us). Pack it: TPB=128, each thread owns a
//   horizontal PIXEL PAIR of the 16x16 tile; du/e/accumulate in f32x2
//   (~17 slots per 2px, LDS per px halved). SPLIT=8 restores occupancy
//   (1024 blocks, single wave, ~28 warps/SM). Merge by last-arriving block
//   per tile via atom.acq_rel.gpu, fixed slice order (deterministic),
//   counter reset for graph replay. Cut at w < 2^-60: abs err ~7e-7 << 1e-3.
// ---------------------------------------------------------------------------

#define HH 128
#define WW 128
#define HWP (HH * WW)
#define FXC 150.0f
#define FYC 150.0f
#define CXC 64.0f
#define CYC 64.0f
#define EPSC 1e-8f

#define TILE    16
#define TX_N    (WW / TILE)          // 8
#define TY_N    (HH / TILE)          // 8
#define TILES   (TX_N * TY_N)        // 64
#define SPLIT   8                    // gaussian slices per tile (power of 2)
#define TPB     128                  // threads per render block (2 px each)
#define PXB     256                  // pixels per tile
#define CHUNK   128                  // gaussians prepped+tested per pass
#define EMIN    (-60.0f)             // log2 weight cutoff

#define MAXB    4

typedef unsigned long long ull;

// per (b, tile, split, pixel) partial sums {den, r, g, b} -- L2 resident
__device__ float4 g_part[MAXB * TILES * SPLIT * PXB];
// per (b, tile) arrival counters (zero-init; reset by merging block)
__device__ int g_cnt[MAXB * TILES];

__device__ __forceinline__ float ex2f(float x) {
    float y;
    asm("ex2.approx.ftz.f32 %0, %1;" : "=f"(y) : "f"(x));
    return y;
}
__device__ __forceinline__ float lg2f(float x) {
    float y;
    asm("lg2.approx.ftz.f32 %0, %1;" : "=f"(y) : "f"(x));
    return y;
}
__device__ __forceinline__ ull pk(float lo, float hi) {
    ull r; asm("mov.b64 %0, {%1, %2};" : "=l"(r) : "f"(lo), "f"(hi)); return r;
}
__device__ __forceinline__ float2 upk(ull v) {
    float2 r; asm("mov.b64 {%0, %1}, %2;" : "=f"(r.x), "=f"(r.y) : "l"(v)); return r;
}
__device__ __forceinline__ ull addx2(ull a, ull b) {
    ull r; asm("add.rn.f32x2 %0, %1, %2;" : "=l"(r) : "l"(a), "l"(b)); return r;
}
__device__ __forceinline__ ull mulx2(ull a, ull b) {
    ull r; asm("mul.rn.f32x2 %0, %1, %2;" : "=l"(r) : "l"(a), "l"(b)); return r;
}
__device__ __forceinline__ ull fmax2(ull a, ull b, ull c) {
    ull r; asm("fma.rn.f32x2 %0, %1, %2, %3;" : "=l"(r) : "l"(a), "l"(b), "l"(c));
    return r;
}
// fetch-add with acq_rel at gpu scope: releases our prior stores, acquires
// peers' released stores. No MEMBAR drain.
__device__ __forceinline__ int atom_add_acqrel(int* p, int v) {
    int old;
    asm volatile("atom.add.acq_rel.gpu.global.s32 %0, [%1], %2;"
                 : "=r"(old) : "l"(p), "r"(v) : "memory");
    return old;
}

// ---------------------------------------------------------------------------
// blockIdx.x = ((b*TILES + tile)*SPLIT + s). 128 threads = one 16x16 tile,
// each thread owns pixels (2k, 2k+1) of one row.
// ---------------------------------------------------------------------------
__global__ void __launch_bounds__(TPB)
render_tiles(float* __restrict__ out,
             const float* __restrict__ pos,
             const float* __restrict__ col,
             const float* __restrict__ opac,
             const float* __restrict__ scal,
             const float* __restrict__ qv,
             const float* __restrict__ tv,
             int N) {
    __shared__ float4 sga[CHUNK];      // u, v, a, bop
    __shared__ float4 sgb[CHUNK];      // cr, cg, cb, -
    __shared__ int s_wbase[TPB / 32];
    __shared__ int s_wcnt[TPB / 32];
    __shared__ int s_total;
    __shared__ int s_arrival;

    const int tid  = threadIdx.x;
    const int bid  = blockIdx.x;
    const int s    = bid & (SPLIT - 1);
    const int tile = (bid / SPLIT) & (TILES - 1);
    const int b    = bid / (SPLIT * TILES);
    const int m    = b * TILES + tile;            // tile slot

    const int tx = tile & (TX_N - 1);
    const int ty = tile / TX_N;
    const int row  = tid >> 3;                    // 0..15
    const int cpr  = tid & 7;                     // column pair 0..7
    const float pyf  = (float)(ty * TILE + row);
    const float px0f = (float)(tx * TILE + cpr * 2);
    const ull   px01 = pk(px0f, px0f + 1.0f);
    const float tcx = (float)(tx * TILE) + 7.5f;   // tile center
    const float tcy = (float)(ty * TILE) + 7.5f;

    // --- per-batch camera, hoisted (broadcast loads, L1 hits) ---
    float qw = qv[b * 4 + 0], qx = qv[b * 4 + 1];
    float qy = qv[b * 4 + 2], qz = qv[b * 4 + 3];
    {
        float inv = rsqrtf(qw * qw + qx * qx + qy * qy + qz * qz);
        qw *= inv; qx *= inv; qy *= inv; qz *= inv;
    }
    const float R00 = 1.0f - 2.0f * (qy * qy + qz * qz);
    const float R01 = 2.0f * (qx * qy - qz * qw);
    const float R02 = 2.0f * (qx * qz + qy * qw);
    const float R10 = 2.0f * (qx * qy + qz * qw);
    const float R11 = 1.0f - 2.0f * (qx * qx + qz * qz);
    const float R12 = 2.0f * (qy * qz - qx * qw);
    const float R20 = 2.0f * (qx * qz - qy * qw);
    const float R21 = 2.0f * (qy * qz + qx * qw);
    const float R22 = 1.0f - 2.0f * (qx * qx + qy * qy);
    const float t0 = tv[b * 3 + 0], t1 = tv[b * 3 + 1], t2 = tv[b * 3 + 2];

    const int lo = (s * N) / SPLIT;
    const int hi = ((s + 1) * N) / SPLIT;

    const int wid  = tid >> 5;
    const int lane = tid & 31;
    const unsigned lanemask_lt = (1u << lane) - 1u;

    ull den01 = 0, ar01 = 0, ag01 = 0, ab01 = 0;

    for (int cb = lo; cb < hi; cb += CHUNK) {
        // --- prep + cull one gaussian per thread ---
        const int j = cb + tid;                    // gaussian index
        bool keep = false;
        float4 ga;
        if (j < hi) {
            const float px = pos[j * 3 + 0];
            const float py = pos[j * 3 + 1];
            const float pz = pos[j * 3 + 2];
            const float cxm = R00 * px + R01 * py + R02 * pz + t0;
            const float cym = R10 * px + R11 * py + R12 * pz + t1;
            const float czm = R20 * px + R21 * py + R22 * pz + t2;
            const float invz = __fdividef(1.0f, czm);
            const float u = cxm * invz * FXC + CXC;
            const float v = cym * invz * FYC + CYC;
            const float sc = scal[j];
            // a = -0.5 * log2(e) / var
            const float a = __fdividef(-0.72134752044448170f, sc * sc);
            const float bop = lg2f(opac[j]);       // opac=0 -> -inf -> culled
            ga = make_float4(u, v, a, bop);

            float dx = fmaxf(fabsf(u - tcx) - 7.5f, 0.0f);
            float dy = fmaxf(fabsf(v - tcy) - 7.5f, 0.0f);
            float mind2 = dx * dx + dy * dy;
            float emax  = fmaf(a, mind2, bop);     // a*mind2 + bop (a<0)
            keep = (emax >= EMIN);
        }

        // --- stable compaction (gaussian-index order preserved) ---
        const unsigned mask = __ballot_sync(0xffffffffu, keep);
        if (lane == 0) s_wcnt[wid] = __popc(mask);
        __syncthreads();
        if (tid == 0) {
            int acc = 0;
            #pragma unroll
            for (int w = 0; w < TPB / 32; w++) { s_wbase[w] = acc; acc += s_wcnt[w]; }
            s_total = acc;
        }
        __syncthreads();
        if (keep) {
            const int posn = s_wbase[wid] + __popc(mask & lanemask_lt);
            sga[posn] = ga;
            sgb[posn] = make_float4(col[j * 3 + 0], col[j * 3 + 1],
                                    col[j * 3 + 2], 0.0f);
        }
        __syncthreads();

        // --- evaluate survivors against this thread's pixel pair (f32x2) ---
        const int cnt = s_total;
        #pragma unroll 4
        for (int t = 0; t < cnt; t++) {
            const float4 A  = sga[t];              // u, v, a, bop (broadcast)
            const float4 Cc = sgb[t];
            // scalar column term (shared by both pixels)
            const float dv = pyf - A.y;
            const float c2 = fmaf(A.z * dv, dv, A.w);
            // packed row terms
            const float mu = -A.x;
            const ull mu2  = pk(mu, mu);
            const ull a2   = pk(A.z, A.z);
            const ull c22  = pk(c2, c2);
            const ull du   = addx2(px01, mu2);
            const ull e    = fmax2(mulx2(a2, du), du, c22);
            const float2 f = upk(e);
            const ull w01  = pk(ex2f(f.x), ex2f(f.y));
            den01 = addx2(den01, w01);
            ar01  = fmax2(w01, pk(Cc.x, Cc.x), ar01);
            ag01  = fmax2(w01, pk(Cc.y, Cc.y), ag01);
            ab01  = fmax2(w01, pk(Cc.z, Cc.z), ab01);
        }
        __syncthreads();
    }

    // --- publish this slice's partials (per-pixel float4) to L2 ---
    {
        const float2 d = upk(den01), r = upk(ar01);
        const float2 g = upk(ag01),  bb = upk(ab01);
        const int pix0 = row * TILE + cpr * 2;
        __stcg(&g_part[bid * PXB + pix0],     make_float4(d.x, r.x, g.x, bb.x));
        __stcg(&g_part[bid * PXB + pix0 + 1], make_float4(d.y, r.y, g.y, bb.y));
    }
    __syncthreads();   // intra-block HB: all stores precede tid0's release

    // --- last-arriving block of this tile merges ---
    if (tid == 0) s_arrival = atom_add_acqrel(&g_cnt[m], 1);
    __syncthreads();   // acquire by tid0 + barrier -> HB for all readers

    if (s_arrival == SPLIT - 1) {
        // all SPLIT partials for tile m visible in L2 (release/acquire chain)
        // fixed slice order -> deterministic regardless of merger identity
        #pragma unroll
        for (int h = 0; h < 2; h++) {
            const int pix = h * TPB + tid;         // pixel within tile
            float4 acc = make_float4(0.f, 0.f, 0.f, 0.f);
            #pragma unroll
            for (int sl = 0; sl < SPLIT; sl++) {
                const float4 p = __ldcg(&g_part[(m * SPLIT + sl) * PXB + pix]);
                acc.x += p.x; acc.y += p.y; acc.z += p.z; acc.w += p.w;
            }
            const float invd = __fdividef(1.0f, acc.x + EPSC);
            const int px = tx * TILE + (pix & (TILE - 1));
            const int py = ty * TILE + (pix / TILE);
            float* ob = out + (size_t)b * 3 * HWP + py * WW + px;
            ob[0]       = acc.y * invd;   // R plane
            ob[HWP]     = acc.z * invd;   // G plane
            ob[2 * HWP] = acc.w * invd;   // B plane
        }
        if (tid == 0) g_cnt[m] = 0;   // reset for next launch / graph replay
    }
}

// ---------------------------------------------------------------------------
extern "C" void kernel_launch(void* const* d_in, const int* in_sizes, int n_in,
                              void* d_out, int out_size) {
    const float* positions = (const float*)d_in[0];
    const float* colors    = (const float*)d_in[1];
    const float* opacities = (const float*)d_in[2];
    const float* scales    = (const float*)d_in[3];
    const float* qvec      = (const float*)d_in[4];
    const float* tvec      = (const float*)d_in[5];
    float* out = (float*)d_out;

    const int N = in_sizes[0] / 3;
    const int B = in_sizes[4] / 4;

    render_tiles<<<B * TILES * SPLIT, TPB>>>(out, positions, colors, opacities,
                                             scales, qvec, tvec, N);
}